// round 1
// baseline (speedup 1.0000x reference)
#include <cuda_runtime.h>
#include <math.h>

#define DD 20
#define TPB 256

typedef unsigned long long u64;

// ---------------- packed f32x2 helpers (sm_100+) ----------------
__device__ __forceinline__ u64 pk(float lo, float hi) {
    u64 r; asm("mov.b64 %0, {%1, %2};" : "=l"(r) : "f"(lo), "f"(hi)); return r;
}
__device__ __forceinline__ void upk(u64 v, float& lo, float& hi) {
    asm("mov.b64 {%0, %1}, %2;" : "=f"(lo), "=f"(hi) : "l"(v));
}
__device__ __forceinline__ u64 fma2(u64 a, u64 b, u64 c) {
    u64 d; asm("fma.rn.f32x2 %0, %1, %2, %3;" : "=l"(d) : "l"(a), "l"(b), "l"(c)); return d;
}
__device__ __forceinline__ u64 add2(u64 a, u64 b) {
    u64 d; asm("add.rn.f32x2 %0, %1, %2;" : "=l"(d) : "l"(a), "l"(b)); return d;
}
__device__ __forceinline__ u64 relu2(u64 v) {
    float a, b; upk(v, a, b);
    return pk(fmaxf(a, 0.0f), fmaxf(b, 0.0f));
}
__device__ __forceinline__ float f4get(const float4& q, int c) {
    switch (c & 3) { case 0: return q.x; case 1: return q.y; case 2: return q.z; default: return q.w; }
}

// ---------------- device-global scratch (no allocation allowed) ----------------
__device__ float2 g_M1[DD * DD];   // M1[k][j] = sum_m W[m,k]*R[m,j], duplicated {m,m}
__device__ float2 g_Wt[DD * DD];   // Wt[k][j] = W[j,k], duplicated {w,w}
__device__ float2 g_c1[DD];        // c1[j] = sum_m b[m]*R[m,j] + 1, dup
__device__ float2 g_bb[DD];        // b[j] dup
__device__ double g_pS[8192];
__device__ double g_pQ[8192];

// ---------------- setup: fold first two linears, duplicate weights ----------------
__global__ void setup_kernel(const float* __restrict__ W,
                             const float* __restrict__ b,
                             const float* __restrict__ R) {
    int i = blockIdx.x * blockDim.x + threadIdx.x;
    if (i < DD * DD) {
        int k = i / DD, j = i % DD;
        float m1 = 0.0f;
        #pragma unroll
        for (int m = 0; m < DD; m++) m1 = fmaf(W[m * DD + k], R[m * DD + j], m1);
        g_M1[i] = make_float2(m1, m1);
        float w = W[j * DD + k];
        g_Wt[i] = make_float2(w, w);
    }
    if (i < DD) {
        float c = 1.0f;
        #pragma unroll
        for (int m = 0; m < DD; m++) c = fmaf(b[m], R[m * DD + i], c);
        g_c1[i] = make_float2(c, c);
        g_bb[i] = make_float2(b[i], b[i]);
    }
}

// ---------------- main: 4 rows/thread, packed f32x2 mainloop ----------------
__global__ void __launch_bounds__(TPB, 1)
main_kernel(const float* __restrict__ x, int B) {
    __shared__ u64 sM1[DD * DD];
    __shared__ u64 sWt[DD * DD];
    __shared__ u64 sc1[DD];
    __shared__ u64 sbb[DD];
    __shared__ double redS[TPB];
    __shared__ double redQ[TPB];

    int tid = threadIdx.x;
    for (int i = tid; i < DD * DD; i += TPB) {
        sM1[i] = ((const u64*)g_M1)[i];
        sWt[i] = ((const u64*)g_Wt)[i];
    }
    if (tid < DD) {
        sc1[tid] = ((const u64*)g_c1)[tid];
        sbb[tid] = ((const u64*)g_bb)[tid];
    }
    __syncthreads();

    long long t    = (long long)blockIdx.x * TPB + tid;
    long long row0 = t * 4;

    float sl = 0.0f, ql = 0.0f;

    if (row0 + 4 <= (long long)B) {
        // load 4 rows of x (320B contiguous, 16B aligned)
        const float4* xp = (const float4*)(x + row0 * DD);
        float4 v[20];
        #pragma unroll
        for (int i = 0; i < 20; i++) v[i] = xp[i];

        // pack rows (0,1) and (2,3) into f32x2 lanes
        u64 xa0[DD], xa1[DD];
        #pragma unroll
        for (int k = 0; k < DD; k++) {
            xa0[k] = pk(f4get(v[k >> 2],      k), f4get(v[5  + (k >> 2)], k));
            xa1[k] = pk(f4get(v[10 + (k >> 2)], k), f4get(v[15 + (k >> 2)], k));
        }

        // ---- stage 1: h2 = relu(x @ M1 + c1) ----
        u64 a0[DD], a1[DD];
        #pragma unroll
        for (int j = 0; j < DD; j++) { a0[j] = sc1[j]; a1[j] = sc1[j]; }
        #pragma unroll
        for (int k = 0; k < DD; k++) {
            u64 x0 = xa0[k], x1 = xa1[k];
            #pragma unroll
            for (int j = 0; j < DD; j++) {
                u64 w = sM1[k * DD + j];
                a0[j] = fma2(x0, w, a0[j]);
                a1[j] = fma2(x1, w, a1[j]);
            }
        }
        #pragma unroll
        for (int j = 0; j < DD; j++) { a0[j] = relu2(a0[j]); a1[j] = relu2(a1[j]); }

        // ---- stage 2: h3 = h2 @ W^T + b ----
        u64 z0[DD], z1[DD];
        #pragma unroll
        for (int j = 0; j < DD; j++) { z0[j] = sbb[j]; z1[j] = sbb[j]; }
        #pragma unroll
        for (int k = 0; k < DD; k++) {
            u64 h0 = a0[k], h1 = a1[k];
            #pragma unroll
            for (int j = 0; j < DD; j++) {
                u64 w = sWt[k * DD + j];
                z0[j] = fma2(h0, w, z0[j]);
                z1[j] = fma2(h1, w, z1[j]);
            }
        }

        // ---- epilogue: packed sum and sum-of-squares ----
        u64 s2 = pk(0.0f, 0.0f), q2 = pk(0.0f, 0.0f);
        #pragma unroll
        for (int j = 0; j < DD; j++) {
            s2 = add2(s2, add2(z0[j], z1[j]));
            q2 = fma2(z0[j], z0[j], q2);
            q2 = fma2(z1[j], z1[j], q2);
        }
        float slo, shi, qlo, qhi;
        upk(s2, slo, shi); upk(q2, qlo, qhi);
        sl = slo + shi;
        ql = qlo + qhi;
    } else if (row0 < (long long)B) {
        // scalar tail (unused when B % 4 == 0, kept for generality)
        for (long long r = row0; r < (long long)B && r < row0 + 4; r++) {
            const float* xr = x + r * DD;
            float h[DD];
            #pragma unroll
            for (int j = 0; j < DD; j++) { float lo, hi; upk(sc1[j], lo, hi); h[j] = lo; (void)hi; }
            for (int k = 0; k < DD; k++) {
                float xv = xr[k];
                #pragma unroll
                for (int j = 0; j < DD; j++) { float lo, hi; upk(sM1[k * DD + j], lo, hi); h[j] = fmaf(xv, lo, h[j]); (void)hi; }
            }
            #pragma unroll
            for (int j = 0; j < DD; j++) h[j] = fmaxf(h[j], 0.0f);
            float z[DD];
            #pragma unroll
            for (int j = 0; j < DD; j++) { float lo, hi; upk(sbb[j], lo, hi); z[j] = lo; (void)hi; }
            for (int k = 0; k < DD; k++) {
                float hv = h[k];
                #pragma unroll
                for (int j = 0; j < DD; j++) { float lo, hi; upk(sWt[k * DD + j], lo, hi); z[j] = fmaf(hv, lo, z[j]); (void)hi; }
            }
            #pragma unroll
            for (int j = 0; j < DD; j++) { sl += z[j]; ql = fmaf(z[j], z[j], ql); }
        }
    }

    // deterministic block reduction
    redS[tid] = (double)sl;
    redQ[tid] = (double)ql;
    __syncthreads();
    for (int s = TPB / 2; s > 0; s >>= 1) {
        if (tid < s) { redS[tid] += redS[tid + s]; redQ[tid] += redQ[tid + s]; }
        __syncthreads();
    }
    if (tid == 0) {
        g_pS[blockIdx.x] = redS[0];
        g_pQ[blockIdx.x] = redQ[0];
    }
}

// ---------------- finalize: deterministic global reduce + scalar postlude ----------------
__global__ void finalize_kernel(float* __restrict__ out, int nblocks) {
    __shared__ double sS[256];
    __shared__ double sQ[256];
    int tid = threadIdx.x;
    double s = 0.0, q = 0.0;
    for (int i = tid; i < nblocks; i += 256) { s += g_pS[i]; q += g_pQ[i]; }
    sS[tid] = s; sQ[tid] = q;
    __syncthreads();
    for (int st = 128; st > 0; st >>= 1) {
        if (tid < st) { sS[tid] += sS[tid + st]; sQ[tid] += sQ[tid + st]; }
        __syncthreads();
    }
    if (tid == 0) {
        double S = sS[0], Q = sQ[0];
        float n = (float)sqrt(Q);
        int k = 0;
        while (n > 1.0f && k < 300) { n *= 0.5f; k++; }   // exact halvings in fp32
        float mult = (n < 0.8f) ? 10.0f : 1.0f;
        double scale = ldexp(1.0, -k);
        out[0] = (float)(S * scale * (double)mult);
    }
}

// ---------------- entry point ----------------
extern "C" void kernel_launch(void* const* d_in, const int* in_sizes, int n_in,
                              void* d_out, int out_size) {
    const float* x = (const float*)d_in[0];
    const float* W = (const float*)d_in[1];
    const float* b = (const float*)d_in[2];
    const float* R = (const float*)d_in[3];
    int B = in_sizes[0] / DD;

    setup_kernel<<<2, 256>>>(W, b, R);

    long long threads = ((long long)B + 3) / 4;
    int nblocks = (int)((threads + TPB - 1) / TPB);
    if (nblocks > 8192) nblocks = 8192;  // safety (B=2e6 -> 1954 blocks)
    main_kernel<<<nblocks, TPB>>>(x, B);

    finalize_kernel<<<1, 256>>>((float*)d_out, nblocks);
}

// round 2
// speedup vs baseline: 1.0893x; 1.0893x over previous
#include <cuda_runtime.h>
#include <math.h>

#define DD  20
#define TPB 128

typedef unsigned long long u64;

// ---------------- packed f32x2 helpers (sm_103a) ----------------
__device__ __forceinline__ u64 pk(float lo, float hi) {
    u64 r; asm("mov.b64 %0, {%1, %2};" : "=l"(r) : "f"(lo), "f"(hi)); return r;
}
__device__ __forceinline__ void upk(u64 v, float& lo, float& hi) {
    asm("mov.b64 {%0, %1}, %2;" : "=f"(lo), "=f"(hi) : "l"(v));
}
__device__ __forceinline__ u64 fma2(u64 a, u64 b, u64 c) {
    u64 d; asm("fma.rn.f32x2 %0, %1, %2, %3;" : "=l"(d) : "l"(a), "l"(b), "l"(c)); return d;
}
__device__ __forceinline__ u64 relu2(u64 v) {
    float a, b; upk(v, a, b);
    return pk(fmaxf(a, 0.0f), fmaxf(b, 0.0f));
}

// ---------------- device-global scratch (no allocation allowed) ----------------
__device__ float2 g_M1[DD * DD];   // folded first-two-linears weights, dup {m,m}
__device__ float2 g_U[DD * DD];    // U = chol(W^T W)^T, upper-tri, dup
__device__ float2 g_c1[DD];        // bias of folded linear (+1), dup
__device__ float2 g_wcs[DD];       // column sums of W, dup
__device__ float2 g_u2[DD];        // 2 * W^T b, dup
__device__ double g_sumb;          // sum(b)
__device__ double g_btb;           // b.b
__device__ double g_pS[16384];
__device__ double g_pQ[16384];

// ---------------- setup: fold linears, Gram + Cholesky ----------------
__global__ void setup_kernel(const float* __restrict__ W,
                             const float* __restrict__ b,
                             const float* __restrict__ R) {
    __shared__ double Gd[DD * DD];
    int tid = threadIdx.x;

    if (tid < DD * DD) {
        int k = tid / DD, j = tid % DD;
        // M1[k][j] = sum_m W[m,k] * R[m,j]
        float m1 = 0.0f;
        #pragma unroll
        for (int m = 0; m < DD; m++) m1 = fmaf(W[m * DD + k], R[m * DD + j], m1);
        g_M1[tid] = make_float2(m1, m1);
        // G[k][j] = sum_m W[m,k] * W[m,j]  (double)
        double g = 0.0;
        #pragma unroll
        for (int m = 0; m < DD; m++) g += (double)W[m * DD + k] * (double)W[m * DD + j];
        Gd[tid] = g;
    }
    if (tid < DD) {
        float c = 1.0f, wcs = 0.0f, u = 0.0f;
        #pragma unroll
        for (int m = 0; m < DD; m++) {
            c   = fmaf(b[m], R[m * DD + tid], c);
            wcs += W[m * DD + tid];
            u   = fmaf(W[m * DD + tid], b[m], u);
        }
        g_c1[tid]  = make_float2(c, c);
        g_wcs[tid] = make_float2(wcs, wcs);
        g_u2[tid]  = make_float2(2.0f * u, 2.0f * u);
    }
    if (tid == 0) {
        double sb = 0.0, bb = 0.0;
        #pragma unroll
        for (int m = 0; m < DD; m++) { sb += (double)b[m]; bb += (double)b[m] * (double)b[m]; }
        g_sumb = sb;
        g_btb  = bb;
    }
    __syncthreads();

    // right-looking Cholesky on Gd (lower part becomes L), parallel updates
    for (int j = 0; j < DD; j++) {
        if (tid == 0) Gd[j * DD + j] = sqrt(Gd[j * DD + j]);
        __syncthreads();
        if (tid > j && tid < DD) Gd[tid * DD + j] /= Gd[j * DD + j];
        __syncthreads();
        if (tid < DD * DD) {
            int i = tid / DD, k = tid % DD;
            if (i > j && k > j && k <= i)
                Gd[i * DD + k] -= Gd[i * DD + j] * Gd[k * DD + j];
        }
        __syncthreads();
    }
    // U[i][k] = L[k][i] for k >= i (upper triangular), zero elsewhere
    if (tid < DD * DD) {
        int i = tid / DD, k = tid % DD;
        float v = (k >= i) ? (float)Gd[k * DD + i] : 0.0f;
        g_U[tid] = make_float2(v, v);
    }
}

// ---------------- main: 4 rows/thread, packed f32x2, no spills ----------------
__global__ void __launch_bounds__(TPB)
main_kernel(const float* __restrict__ x, int B) {
    __shared__ __align__(16) u64 sM1[DD * DD];
    __shared__ __align__(16) u64 sU[DD * DD];
    __shared__ u64 sc1[DD];
    __shared__ __align__(16) u64 swcs[DD];
    __shared__ __align__(16) u64 su2[DD];
    __shared__ double redS[TPB];
    __shared__ double redQ[TPB];

    int tid = threadIdx.x;
    for (int i = tid; i < DD * DD; i += TPB) {
        sM1[i] = ((const u64*)g_M1)[i];
        sU[i]  = ((const u64*)g_U)[i];
    }
    if (tid < DD) {
        sc1[tid]  = ((const u64*)g_c1)[tid];
        swcs[tid] = ((const u64*)g_wcs)[tid];
        su2[tid]  = ((const u64*)g_u2)[tid];
    }
    __syncthreads();

    long long t    = (long long)blockIdx.x * TPB + tid;
    long long row0 = t * 4;

    float sl = 0.0f, ql = 0.0f;

    if (row0 + 4 <= (long long)B) {
        // Build packed rows directly from float4 loads — at most 4 float4 live.
        const float4* xp = (const float4*)(x + row0 * DD);
        u64 xa0[DD], xa1[DD];   // rows (0,1) and (2,3)
        #pragma unroll
        for (int i = 0; i < 5; i++) {
            float4 A  = xp[i];
            float4 Bv = xp[5 + i];
            float4 C  = xp[10 + i];
            float4 Dv = xp[15 + i];
            xa0[4*i+0] = pk(A.x, Bv.x);  xa1[4*i+0] = pk(C.x, Dv.x);
            xa0[4*i+1] = pk(A.y, Bv.y);  xa1[4*i+1] = pk(C.y, Dv.y);
            xa0[4*i+2] = pk(A.z, Bv.z);  xa1[4*i+2] = pk(C.z, Dv.z);
            xa0[4*i+3] = pk(A.w, Bv.w);  xa1[4*i+3] = pk(C.w, Dv.w);
        }

        // ---- stage 1: h2 = relu(x @ M1 + c1) ----
        u64 a0[DD], a1[DD];
        #pragma unroll
        for (int j = 0; j < DD; j++) { a0[j] = sc1[j]; a1[j] = sc1[j]; }
        const ulonglong2* sM1v = (const ulonglong2*)sM1;
        #pragma unroll
        for (int k = 0; k < DD; k++) {
            u64 x0 = xa0[k], x1 = xa1[k];
            #pragma unroll
            for (int jp = 0; jp < DD / 2; jp++) {
                ulonglong2 w = sM1v[k * (DD / 2) + jp];
                a0[2*jp+0] = fma2(x0, w.x, a0[2*jp+0]);
                a1[2*jp+0] = fma2(x1, w.x, a1[2*jp+0]);
                a0[2*jp+1] = fma2(x0, w.y, a0[2*jp+1]);
                a1[2*jp+1] = fma2(x1, w.y, a1[2*jp+1]);
            }
        }
        #pragma unroll
        for (int j = 0; j < DD; j++) { a0[j] = relu2(a0[j]); a1[j] = relu2(a1[j]); }
        // xa0/xa1 dead here — peak live stays ~160 regs

        // ---- S and Q-linear parts: wcs.h2 and (2 W^T b).h2 ----
        u64 s20 = 0ULL, s21 = 0ULL, q20 = 0ULL, q21 = 0ULL;
        const ulonglong2* swcsv = (const ulonglong2*)swcs;
        const ulonglong2* su2v  = (const ulonglong2*)su2;
        #pragma unroll
        for (int kp = 0; kp < DD / 2; kp++) {
            ulonglong2 wc = swcsv[kp];
            ulonglong2 uu = su2v[kp];
            s20 = fma2(a0[2*kp+0], wc.x, s20);  s20 = fma2(a0[2*kp+1], wc.y, s20);
            s21 = fma2(a1[2*kp+0], wc.x, s21);  s21 = fma2(a1[2*kp+1], wc.y, s21);
            q20 = fma2(a0[2*kp+0], uu.x, q20);  q20 = fma2(a0[2*kp+1], uu.y, q20);
            q21 = fma2(a1[2*kp+0], uu.x, q21);  q21 = fma2(a1[2*kp+1], uu.y, q21);
        }

        // ---- Q quadratic part: ||U h2||^2, U upper-triangular ----
        #pragma unroll
        for (int i = 0; i < DD; i++) {
            u64 y0 = 0ULL, y1 = 0ULL;
            const int ks = i & ~1;   // row i of U is zero below diag; padded start even
            #pragma unroll
            for (int k = ks; k < DD; k += 2) {
                ulonglong2 w = *(const ulonglong2*)&sU[i * DD + k];
                y0 = fma2(a0[k],     w.x, y0);
                y0 = fma2(a0[k + 1], w.y, y0);
                y1 = fma2(a1[k],     w.x, y1);
                y1 = fma2(a1[k + 1], w.y, y1);
            }
            q20 = fma2(y0, y0, q20);
            q21 = fma2(y1, y1, q21);
        }

        float slo, shi, qlo, qhi;
        upk(s20, slo, shi); sl  = slo + shi;
        upk(s21, slo, shi); sl += slo + shi;
        upk(q20, qlo, qhi); ql  = qlo + qhi;
        upk(q21, qlo, qhi); ql += qlo + qhi;
    } else if (row0 < (long long)B) {
        // scalar tail (unused for B % 4 == 0, kept for generality)
        for (long long r = row0; r < (long long)B && r < row0 + 4; r++) {
            const float* xr = x + r * DD;
            float h[DD];
            #pragma unroll
            for (int j = 0; j < DD; j++) { float lo, hi; upk(sc1[j], lo, hi); h[j] = lo; (void)hi; }
            for (int k = 0; k < DD; k++) {
                float xv = xr[k];
                #pragma unroll
                for (int j = 0; j < DD; j++) { float lo, hi; upk(sM1[k * DD + j], lo, hi); h[j] = fmaf(xv, lo, h[j]); (void)hi; }
            }
            #pragma unroll
            for (int j = 0; j < DD; j++) h[j] = fmaxf(h[j], 0.0f);
            #pragma unroll
            for (int k = 0; k < DD; k++) {
                float wl, wh, ul, uh;
                upk(swcs[k], wl, wh); (void)wh;
                upk(su2[k],  ul, uh); (void)uh;
                sl = fmaf(h[k], wl, sl);
                ql = fmaf(h[k], ul, ql);
            }
            for (int i = 0; i < DD; i++) {
                float y = 0.0f;
                for (int k = i; k < DD; k++) {
                    float wl, wh; upk(sU[i * DD + k], wl, wh); (void)wh;
                    y = fmaf(h[k], wl, y);
                }
                ql = fmaf(y, y, ql);
            }
        }
    }

    // deterministic block reduction
    redS[tid] = (double)sl;
    redQ[tid] = (double)ql;
    __syncthreads();
    for (int s = TPB / 2; s > 0; s >>= 1) {
        if (tid < s) { redS[tid] += redS[tid + s]; redQ[tid] += redQ[tid + s]; }
        __syncthreads();
    }
    if (tid == 0) {
        g_pS[blockIdx.x] = redS[0];
        g_pQ[blockIdx.x] = redQ[0];
    }
}

// ---------------- finalize: global reduce + scalar postlude ----------------
__global__ void finalize_kernel(float* __restrict__ out, int nblocks, int B) {
    __shared__ double sS[256];
    __shared__ double sQ[256];
    int tid = threadIdx.x;
    double s = 0.0, q = 0.0;
    for (int i = tid; i < nblocks; i += 256) { s += g_pS[i]; q += g_pQ[i]; }
    sS[tid] = s; sQ[tid] = q;
    __syncthreads();
    for (int st = 128; st > 0; st >>= 1) {
        if (tid < st) { sS[tid] += sS[tid + st]; sQ[tid] += sQ[tid + st]; }
        __syncthreads();
    }
    if (tid == 0) {
        double S = sS[0] + (double)B * g_sumb;
        double Q = sQ[0] + (double)B * g_btb;
        float n = (float)sqrt(Q);
        int k = 0;
        while (n > 1.0f && k < 300) { n *= 0.5f; k++; }   // exact halvings in fp32
        float mult = (n < 0.8f) ? 10.0f : 1.0f;
        double scale = ldexp(1.0, -k);
        out[0] = (float)(S * scale * (double)mult);
    }
}

// ---------------- entry point ----------------
extern "C" void kernel_launch(void* const* d_in, const int* in_sizes, int n_in,
                              void* d_out, int out_size) {
    const float* x = (const float*)d_in[0];
    const float* W = (const float*)d_in[1];
    const float* b = (const float*)d_in[2];
    const float* R = (const float*)d_in[3];
    int B = in_sizes[0] / DD;

    setup_kernel<<<1, 512>>>(W, b, R);

    long long threads = ((long long)B + 3) / 4;
    int nblocks = (int)((threads + TPB - 1) / TPB);
    if (nblocks > 16384) nblocks = 16384;  // B=2e6 -> 3907 blocks
    main_kernel<<<nblocks, TPB>>>(x, B);

    finalize_kernel<<<1, 256>>>((float*)d_out, nblocks, B);
}